// round 17
// baseline (speedup 1.0000x reference)
#include <cuda_runtime.h>
#include <math.h>

// EdgeAttr: out[e][c] = sigmoid( sum_k exp(-(((d_e - 0.4k)/0.375)^2)) * W[k][c] + b[c] )
// Inputs: pos [N,3] f32, edge_index [2,E] int32, W [16,128] f32, b [128] f32
// Output: [E,128] f32
//
// R14 resubmit (prior round was an infra failure, kernel never ran):
//      occupancy push. Lane owns 2 cols (32 W regs) -> 3 blocks/SM; warp-pairs split
//      each edge's 128 cols; horizontal (even,odd) f32x2 accumulation feeds packed
//      multiplicands straight from ld.shared.v2.b64 on the contiguous rbf row.
//      -log2(e) folded into W,b so sigmoid = rcp(1+ex2(z)) with no FMUL.
//      No gather pipeline (occupancy hides latency); double-buffered tile.

#define THREADS 256
#define E_TILE  64
#define HID     128
#define DC      16
#define NL2E    (-1.4426950408889634f)

__device__ __forceinline__ unsigned long long pack2(float lo, float hi) {
    unsigned long long r;
    asm("mov.b64 %0, {%1, %2};" : "=l"(r) : "f"(lo), "f"(hi));
    return r;
}
__device__ __forceinline__ void unpack2(unsigned long long v, float& lo, float& hi) {
    asm("mov.b64 {%0, %1}, %2;" : "=f"(lo), "=f"(hi) : "l"(v));
}
__device__ __forceinline__ unsigned long long fma2(unsigned long long a,
                                                   unsigned long long b,
                                                   unsigned long long c) {
    unsigned long long d;
    asm("fma.rn.f32x2 %0, %1, %2, %3;" : "=l"(d) : "l"(a), "l"(b), "l"(c));
    return d;
}
__device__ __forceinline__ float sigmoid_z(float z) {
    // z = -x*log2(e) already; sigmoid(x) = 1 / (1 + 2^z) : EX2 + FADD + RCP
    float e, r;
    asm("ex2.approx.f32 %0, %1;" : "=f"(e) : "f"(z));
    asm("rcp.approx.f32 %0, %1;" : "=f"(r) : "f"(1.0f + e));
    return r;
}

__global__ __launch_bounds__(THREADS, 3)
void edge_attr_kernel(const float* __restrict__ pos,
                      const int* __restrict__ edge_index,
                      const float* __restrict__ W,
                      const float* __restrict__ bias,
                      float* __restrict__ out,
                      int n_edges, int n_tiles)
{
    // Contiguous RBF tile (proven layout): sR[buf][edge][k], 64 B/edge.  8 KB.
    __shared__ __align__(16) float sR[2][E_TILE][DC];

    const int t    = threadIdx.x;
    const int lane = t & 31;
    const int w    = t >> 5;          // warp 0..7
    const int half = w & 1;           // column half
    const int eg   = w >> 1;          // edge group 0..3 (16 edges each)
    const int c    = half * 64 + lane * 2;   // this lane's 2 output columns

    // ---- W' = -log2e * W, packed by k-pairs; 16 b64 = 32 regs ----
    // wp[2*j+col] = (W'[2j][c+col], W'[2j+1][c+col]), j = 0..7
    unsigned long long wp[DC];
    #pragma unroll
    for (int j = 0; j < DC / 2; j++) {
        const float2 w0 = *reinterpret_cast<const float2*>(W + (2 * j)     * HID + c);
        const float2 w1 = *reinterpret_cast<const float2*>(W + (2 * j + 1) * HID + c);
        wp[2 * j + 0] = pack2(NL2E * w0.x, NL2E * w1.x);
        wp[2 * j + 1] = pack2(NL2E * w0.y, NL2E * w1.y);
    }
    unsigned long long binit0, binit1;
    {
        const float2 bv = *reinterpret_cast<const float2*>(bias + c);
        binit0 = pack2(NL2E * bv.x, 0.0f);
        binit1 = pack2(NL2E * bv.y, 0.0f);
    }

    // Phase-1 role: 4 threads per edge, each computes 4 RBF terms
    const int el = t >> 2;            // local edge 0..63
    const int q  = t & 3;             // quarter 0..3

    int buf = 0;
    for (int tile = blockIdx.x; tile < n_tiles; tile += gridDim.x) {
        // ---- phase 1: gather + RBF (latency hidden by 6 warps/SMSP) ----
        {
            const int ge = min(tile * E_TILE + el, n_edges - 1);
            const int ia = edge_index[ge];
            const int ib = edge_index[n_edges + ge];
            const float pax = pos[3 * ia], pay = pos[3 * ia + 1], paz = pos[3 * ia + 2];
            const float pbx = pos[3 * ib], pby = pos[3 * ib + 1], pbz = pos[3 * ib + 2];
            const float dx = pax - pbx, dy = pay - pby, dz = paz - pbz;
            const float d  = sqrtf(fmaf(dx, dx, fmaf(dy, dy, dz * dz)));
            float r[4];
            #pragma unroll
            for (int j4 = 0; j4 < 4; j4++) {
                const float u = (d - 0.4f * (float)(q * 4 + j4)) * 2.6666666667f;
                r[j4] = __expf(-u * u);
            }
            *reinterpret_cast<float4*>(&sR[buf][el][q * 4]) =
                make_float4(r[0], r[1], r[2], r[3]);
        }
        __syncthreads();

        // ---- phase 2: 16 edges per warp, 2 cols per lane ----
        const int e0 = tile * E_TILE;
        #pragma unroll
        for (int p = 0; p < 16; p++) {
            const int elx = eg * 16 + p;
            const int ge  = e0 + elx;

            const unsigned int sb =
                (unsigned int)__cvta_generic_to_shared(&sR[buf][elx][0]);

            unsigned long long a0 = binit0, a1 = binit1;
            #pragma unroll
            for (int jj = 0; jj < 4; jj++) {
                unsigned long long p0, p1;  // (r_{4jj},r_{4jj+1}), (r_{4jj+2},r_{4jj+3})
                asm volatile("ld.shared.v2.b64 {%0, %1}, [%2];"
                             : "=l"(p0), "=l"(p1) : "r"(sb + jj * 16));
                a0 = fma2(p0, wp[4 * jj + 0], a0);
                a1 = fma2(p0, wp[4 * jj + 1], a1);
                a0 = fma2(p1, wp[4 * jj + 2], a0);
                a1 = fma2(p1, wp[4 * jj + 3], a1);
            }

            float lo, hi;
            unpack2(a0, lo, hi); const float z0 = lo + hi;
            unpack2(a1, lo, hi); const float z1 = lo + hi;
            const float2 o = make_float2(sigmoid_z(z0), sigmoid_z(z1));
            if (ge < n_edges)
                __stcs(reinterpret_cast<float2*>(out + (size_t)ge * HID + c), o);
        }
        __syncthreads();   // protect sR[buf] before next phase-1 overwrite of other buf
        buf ^= 1;
    }
}

extern "C" void kernel_launch(void* const* d_in, const int* in_sizes, int n_in,
                              void* d_out, int out_size)
{
    const float* pos = (const float*)d_in[0];
    const int*   ei  = (const int*)d_in[1];
    const float* W   = (const float*)d_in[2];
    const float* b   = (const float*)d_in[3];
    float*       out = (float*)d_out;

    const int n_edges = out_size / HID;
    const int n_tiles = (n_edges + E_TILE - 1) / E_TILE;
    int blocks = 148 * 3;                    // persistent grid, 3 blocks/SM
    if (blocks > n_tiles) blocks = n_tiles;

    edge_attr_kernel<<<blocks, THREADS>>>(pos, ei, W, b, out, n_edges, n_tiles);
}